// round 14
// baseline (speedup 1.0000x reference)
#include <cuda_runtime.h>
#include <cuda_fp16.h>
#include <cstdint>

// SuperchargingBKT — round 13 (= round 12 retry; R12 bench died to infra).
//
// Persistent CTAs, full (omega,sigma) table in shared memory.
// Model: runtime floor = l1tex slot throughput of the random gathers
// (ability ~32 wf + pshalf ~25 wf per warp-gather). pshalf's table is 200KB
// as half2 -> fits in ONE SM's smem. Persistent single-wave launch (128 CTAs
// x 512 thr, 4 rows/warp, perfectly balanced) stages it once; the random
// pshalf gather becomes a ~5-phase LDS instead of ~25 L1 wavefronts.
// Row body unchanged from R11 (warp-per-row SEG=16, tanh.approx sigmoid,
// reg coefficients).
//
// Inputs (metadata order):
//  0 pL0_logit [K] f32   4 pS_logit [K] f32    8 observations [B,T] i32
//  1 pT_logit  [K] f32   5 omega    [P] f32    9 kc_ids       [B,T] i32
//  2 pF_logit  [K] f32   6 sigma    [P] f32   10 problem_ids  [B,T] i32
//  3 pG_logit  [K] f32   7 ability  [S,4] f32 11 student_ids  [B,T] i32
// Output: p_correct [B,T] f32

constexpr int T_LEN = 512;
constexpr int SEG   = 16;              // steps per lane (32 lanes x 16 = 512)
constexpr int THREADS = 512;           // 16 warps per CTA
constexpr int ROWS_PER_WARP = 4;
constexpr int ROWS_PER_CTA  = (THREADS / 32) * ROWS_PER_WARP;   // 64
constexpr int K_CAP = 1024;            // K = 1000
constexpr int P_CAP = 50048;           // P = 50000 (16B-aligned pad)

constexpr int SMEM_PS_BYTES = P_CAP * 4;                  // 200192 B half2
constexpr int SMEM_KC_BYTES = K_CAP * 16;                 // 16384 B float4
constexpr int SMEM_TOTAL    = SMEM_PS_BYTES + SMEM_KC_BYTES;   // 216576 B

__device__ __half2 g_pshalf[P_CAP];    // (omega,sigma) per problem, fp16

// single-MUFU sigmoid: sigma(x) = 0.5*tanh(0.5x) + 0.5
__device__ __forceinline__ float sigmoidf(float x) {
    float t;
    asm("tanh.approx.f32 %0, %1;" : "=f"(t) : "f"(x * 0.5f));
    return fmaf(t, 0.5f, 0.5f);
}

__global__ void pack_ps(
    const float* __restrict__ omega, const float* __restrict__ sigma, int P)
{
    int i = blockIdx.x * blockDim.x + threadIdx.x;
    if (i < P)
        g_pshalf[i] = __floats2half2_rn(omega[i], sigma[i]);
}

__global__ void __launch_bounds__(THREADS, 1)
bkt_warp_scan(
    const float* __restrict__ pL0_logit,
    const float* __restrict__ pT_logit,
    const float* __restrict__ pF_logit,
    const float* __restrict__ pG_logit,
    const float* __restrict__ pS_logit,
    const float4* __restrict__ ability,
    const int*  __restrict__ obs,
    const int*  __restrict__ kc,
    const int*  __restrict__ pid,
    const int*  __restrict__ sid,
    float* __restrict__ out,
    int B, int K)
{
    extern __shared__ char smem[];
    __half2* psTab = reinterpret_cast<__half2*>(smem);                  // [P_CAP]
    float4*  kcTab = reinterpret_cast<float4*>(smem + SMEM_PS_BYTES);   // [K_CAP]

    const int tid  = threadIdx.x;
    const int lane = tid & 31;
    const int wid  = tid >> 5;

    // ---- stage tables once (persistent single wave) -----------------------
    {   // ps table: vectorized 16B copies (4 half2 per uint4)
        const uint4* src = reinterpret_cast<const uint4*>(g_pshalf);
        uint4* dst = reinterpret_cast<uint4*>(psTab);
        for (int i = tid; i < P_CAP / 4; i += THREADS) dst[i] = src[i];
    }
    for (int i = tid; i < K; i += THREADS)
        kcTab[i] = make_float4(pT_logit[i], pF_logit[i], pG_logit[i], pS_logit[i]);
    __syncthreads();

    const int warpGlobal = blockIdx.x * (THREADS / 32) + wid;

    for (int r = 0; r < ROWS_PER_WARP; ++r) {
        const int row = warpGlobal * ROWS_PER_WARP + r;
        if (row >= B) break;                 // no syncs below: safe

        const int base = row * T_LEN;
        const int s0   = base + lane * SEG;

        float C1[SEG], C2[SEG], C3[SEG], C4[SEG];
        unsigned obits = 0;

        float a00 = 1.f, a01 = 0.f, a10 = 0.f, a11 = 1.f;

        // ---- pass 1: coefficients + segment matrix product ---------------
#pragma unroll
        for (int q = 0; q < SEG / 4; ++q) {
            const int o4i = s0 + 4 * q;
            int4 kv = *reinterpret_cast<const int4*>(kc  + o4i);
            int4 pv = *reinterpret_cast<const int4*>(pid + o4i);
            int4 sv = *reinterpret_cast<const int4*>(sid + o4i);
            int4 ov = *reinterpret_cast<const int4*>(obs + o4i);
            int kk[4] = {kv.x, kv.y, kv.z, kv.w};
            int pp[4] = {pv.x, pv.y, pv.z, pv.w};
            int ssx[4]= {sv.x, sv.y, sv.z, sv.w};
            int oo[4] = {ov.x, ov.y, ov.z, ov.w};

#pragma unroll
            for (int j = 0; j < 4; ++j) {
                const int i = 4 * q + j;
                float4 th  = __ldg(ability + ssx[j]);      // random L2/L1 LDG
                float4 kcp = kcTab[kk[j]];                 // LDS.128
                float2 psp = __half22float2(psTab[pp[j]]); // LDS 4B (was LDG)
                float pT = sigmoidf(kcp.x + th.x);
                float pF = sigmoidf(kcp.y - th.y);
                float pG = sigmoidf(kcp.z + psp.x + th.z);
                float pS = sigmoidf(kcp.w + psp.y - th.w);
                bool o = (oo[j] != 0);
                float pom = o ? (1.0f - pS) : pS;      // P(y | mastered)
                float pou = o ? pG : (1.0f - pG);      // P(y | unmastered)
                float c1 = (1.0f - pF) * pom;
                float c2 = pT * pou;
                float c3 = pF * pom;
                float c4 = (1.0f - pT) * pou;
                C1[i] = c1; C2[i] = c2; C3[i] = c3; C4[i] = c4;
                obits |= (o ? 1u : 0u) << i;

                // A = M * A,  M = [[c4,c3],[c2,c1]]
                float n00 = fmaf(c4, a00, c3 * a10);
                float n01 = fmaf(c4, a01, c3 * a11);
                float n10 = fmaf(c2, a00, c1 * a10);
                float n11 = fmaf(c2, a01, c1 * a11);
                a00 = n00; a01 = n01; a10 = n10; a11 = n11;
            }
            if (q & 1) {   // normalize every 8 steps (projective scale free)
                float rn = __fdividef(1.0f, a00 + a01 + a10 + a11);
                a00 *= rn; a01 *= rn; a10 *= rn; a11 *= rn;
            }
        }

        // ---- inclusive warp scan of segment matrices ----------------------
#pragma unroll
        for (int d = 1; d < 32; d <<= 1) {
            float b00 = __shfl_up_sync(0xFFFFFFFFu, a00, d);
            float b01 = __shfl_up_sync(0xFFFFFFFFu, a01, d);
            float b10 = __shfl_up_sync(0xFFFFFFFFu, a10, d);
            float b11 = __shfl_up_sync(0xFFFFFFFFu, a11, d);
            if (lane >= d) {
                float n00 = fmaf(a00, b00, a01 * b10);  // mine(later)*other(earlier)
                float n01 = fmaf(a00, b01, a01 * b11);
                float n10 = fmaf(a10, b00, a11 * b10);
                float n11 = fmaf(a10, b01, a11 * b11);
                float rn = __fdividef(1.0f, n00 + n01 + n10 + n11);
                a00 = n00 * rn; a01 = n01 * rn; a10 = n10 * rn; a11 = n11 * rn;
            }
        }

        // exclusive prefix
        float e00 = __shfl_up_sync(0xFFFFFFFFu, a00, 1);
        float e01 = __shfl_up_sync(0xFFFFFFFFu, a01, 1);
        float e10 = __shfl_up_sync(0xFFFFFFFFu, a10, 1);
        float e11 = __shfl_up_sync(0xFFFFFFFFu, a11, 1);
        if (lane == 0) { e00 = 1.f; e01 = 0.f; e10 = 0.f; e11 = 1.f; }

        // initial state from pL0 at first KC (uniform broadcast load)
        float pL0 = sigmoidf(__ldg(pL0_logit + __ldg(kc + base)));
        float hu0 = 1.0f - pL0;
        float hm0 = pL0;
        float hu = fmaf(e00, hu0, e01 * hm0);
        float hm = fmaf(e10, hu0, e11 * hm0);
        float rs = __fdividef(1.0f, hu + hm);
        hu *= rs; hm *= rs;

        // ---- pass 2: replay segment, emit p_correct -----------------------
        float* op = out + s0;
#pragma unroll
        for (int q = 0; q < SEG / 4; ++q) {
            float4 res;
            float* r4 = reinterpret_cast<float*>(&res);
#pragma unroll
            for (int j = 0; j < 4; ++j) {
                const int i = 4 * q + j;
                float nm = fmaf(C1[i], hm, C2[i] * hu);
                float nu = fmaf(C3[i], hm, C4[i] * hu);
                float rn = __fdividef(1.0f, nm + nu);
                hm = nm * rn;
                hu = nu * rn;
                bool o = (obits >> i) & 1u;
                float pom = C1[i] + C3[i];             // = 1-pS if o else pS
                float pou = C2[i] + C4[i];             // = pG   if o else 1-pG
                float c5 = o ? pom : (1.0f - pom);     // 1-pS
                float c6 = o ? pou : (1.0f - pou);     // pG
                r4[j] = fmaf(c5, hm, c6 * hu);
            }
            *reinterpret_cast<float4*>(op + 4 * q) = res;
        }
    }
}

extern "C" void kernel_launch(void* const* d_in, const int* in_sizes, int n_in,
                              void* d_out, int out_size) {
    const float* pL0 = (const float*)d_in[0];
    const float* pT  = (const float*)d_in[1];
    const float* pF  = (const float*)d_in[2];
    const float* pG  = (const float*)d_in[3];
    const float* pS  = (const float*)d_in[4];
    const float* om  = (const float*)d_in[5];
    const float* sg  = (const float*)d_in[6];
    const float4* ab = (const float4*)d_in[7];
    const int* obs = (const int*)d_in[8];
    const int* kc  = (const int*)d_in[9];
    const int* pid = (const int*)d_in[10];
    const int* sid = (const int*)d_in[11];
    float* out = (float*)d_out;

    int K = in_sizes[0];                  // 1000
    int P = in_sizes[5];                  // 50000
    int B = in_sizes[8] / T_LEN;          // 8192 rows
    if (K > K_CAP) K = K_CAP;
    if (P > P_CAP) P = P_CAP;
    if (P < 1) P = 1;

    cudaFuncSetAttribute(bkt_warp_scan,
                         cudaFuncAttributeMaxDynamicSharedMemorySize, SMEM_TOTAL);

    pack_ps<<<(P + 511) / 512, 512>>>(om, sg, P);

    int grid = (B + ROWS_PER_CTA - 1) / ROWS_PER_CTA;   // 128 for B=8192
    bkt_warp_scan<<<grid, THREADS, SMEM_TOTAL>>>(pL0, pT, pF, pG, pS, ab,
                                                 obs, kc, pid, sid, out, B, K);
}

// round 15
// speedup vs baseline: 1.2494x; 1.2494x over previous
#include <cuda_runtime.h>
#include <cuda_fp16.h>
#include <cstdint>

// SuperchargingBKT — round 14: R11 body at 32 warps/SM.
//
// R13 lesson: L1 work is ~30us regardless of gather mechanism; wall time
// tracks latency coverage (warps x MLP) above that floor. R11 (24 warps,
// 78 regs) = 55.6us. R14 frees registers by moving the replay coefficient
// cache to static shared (sC[8][4][256], thread-private, conflict-free)
// -> regs <= 64 -> __launch_bounds__(256,4) -> 32 warps/SM.
// Body otherwise identical to R11: 2 warps/row (SEG=8), tanh.approx
// sigmoid, kc table staged in smem from source arrays, (omega,sigma) as
// fp16 __device__ table (L1-resident).
//
// Inputs (metadata order):
//  0 pL0_logit [K] f32   4 pS_logit [K] f32    8 observations [B,T] i32
//  1 pT_logit  [K] f32   5 omega    [P] f32    9 kc_ids       [B,T] i32
//  2 pF_logit  [K] f32   6 sigma    [P] f32   10 problem_ids  [B,T] i32
//  3 pG_logit  [K] f32   7 ability  [S,4] f32 11 student_ids  [B,T] i32
// Output: p_correct [B,T] f32

constexpr int T_LEN = 512;
constexpr int SEG   = 8;               // steps per lane (2 warps x 32 x 8)
constexpr int HALF  = 256;             // steps per warp
constexpr int THREADS = 256;           // 8 warps = 4 rows per CTA
constexpr int ROWS_PER_CTA = 4;
constexpr int K_CAP = 1000;            // K = 1000 exactly (static smem budget)
constexpr int P_CAP = 50048;           // P = 50000

__device__ __half2 g_pshalf[P_CAP];    // (omega,sigma) per problem, fp16

// single-MUFU sigmoid: sigma(x) = 0.5*tanh(0.5x) + 0.5
__device__ __forceinline__ float sigmoidf(float x) {
    float t;
    asm("tanh.approx.f32 %0, %1;" : "=f"(t) : "f"(x * 0.5f));
    return fmaf(t, 0.5f, 0.5f);
}

__global__ void pack_ps(
    const float* __restrict__ omega, const float* __restrict__ sigma, int P)
{
    int i = blockIdx.x * blockDim.x + threadIdx.x;
    if (i < P)
        g_pshalf[i] = __floats2half2_rn(omega[i], sigma[i]);
}

__global__ void __launch_bounds__(THREADS, 4)
bkt_warp_scan(
    const float* __restrict__ pL0_logit,
    const float* __restrict__ pT_logit,
    const float* __restrict__ pF_logit,
    const float* __restrict__ pG_logit,
    const float* __restrict__ pS_logit,
    const float4* __restrict__ ability,
    const int*  __restrict__ obs,
    const int*  __restrict__ kc,
    const int*  __restrict__ pid,
    const int*  __restrict__ sid,
    float* __restrict__ out,
    int B, int K)
{
    __shared__ float4 kcTab[K_CAP];                  // 16000 B
    __shared__ float  sC[SEG][4][THREADS];           // 32768 B, thread-private
    __shared__ float4 w0tot[ROWS_PER_CTA];           // 64 B

    const int tid  = threadIdx.x;
    const int lane = tid & 31;
    const int wid  = tid >> 5;                   // 0..7
    const int rowInCta  = wid >> 1;              // 0..3
    const int warpInRow = wid & 1;               // 0 = steps 0-255, 1 = 256-511
    const int row  = blockIdx.x * ROWS_PER_CTA + rowInCta;

    // stage kc table directly from source arrays (coalesced, L2-hot)
    for (int i = tid; i < K; i += THREADS)
        kcTab[i] = make_float4(pT_logit[i], pF_logit[i], pG_logit[i], pS_logit[i]);
    __syncthreads();

    const int base = row * T_LEN;
    const int s0   = base + warpInRow * HALF + lane * SEG;

    // ---- front-load indices for this lane's 8 steps -----------------------
    int4 kv0 = *reinterpret_cast<const int4*>(kc  + s0);
    int4 kv1 = *reinterpret_cast<const int4*>(kc  + s0 + 4);
    int4 pv0 = *reinterpret_cast<const int4*>(pid + s0);
    int4 pv1 = *reinterpret_cast<const int4*>(pid + s0 + 4);
    int4 sv0 = *reinterpret_cast<const int4*>(sid + s0);
    int4 sv1 = *reinterpret_cast<const int4*>(sid + s0 + 4);
    int4 ov0 = *reinterpret_cast<const int4*>(obs + s0);
    int4 ov1 = *reinterpret_cast<const int4*>(obs + s0 + 4);

    int kk[SEG] = {kv0.x, kv0.y, kv0.z, kv0.w, kv1.x, kv1.y, kv1.z, kv1.w};
    int pp[SEG] = {pv0.x, pv0.y, pv0.z, pv0.w, pv1.x, pv1.y, pv1.z, pv1.w};
    int ssx[SEG]= {sv0.x, sv0.y, sv0.z, sv0.w, sv1.x, sv1.y, sv1.z, sv1.w};
    unsigned obits = 0;
    {
        int oo[SEG] = {ov0.x, ov0.y, ov0.z, ov0.w, ov1.x, ov1.y, ov1.z, ov1.w};
#pragma unroll
        for (int i = 0; i < SEG; ++i) obits |= (oo[i] != 0 ? 1u : 0u) << i;
    }

    // ph cheap to front-load fully (1 reg each)
    __half2 ph[SEG];
#pragma unroll
    for (int i = 0; i < SEG; ++i) ph[i] = __ldg(&g_pshalf[pp[i]]);

    // initial state from pL0 at first KC (uniform broadcast load)
    float pL0 = sigmoidf(__ldg(pL0_logit + __ldg(kc + base)));

    // ---- pass 1: coefficients (to sC) + segment matrix product ------------
    // th gathers staged 4 at a time to keep peak registers under the 64 cap.
    float a00 = 1.f, a01 = 0.f, a10 = 0.f, a11 = 1.f;
#pragma unroll
    for (int h = 0; h < 2; ++h) {
        float4 th[4];
#pragma unroll
        for (int j = 0; j < 4; ++j) th[j] = __ldg(ability + ssx[4 * h + j]);
#pragma unroll
        for (int j = 0; j < 4; ++j) {
            const int i = 4 * h + j;
            float4 kcp = kcTab[kk[i]];               // LDS.128
            float2 psp = __half22float2(ph[i]);
            float pT = sigmoidf(kcp.x + th[j].x);
            float pF = sigmoidf(kcp.y - th[j].y);
            float pG = sigmoidf(kcp.z + psp.x + th[j].z);
            float pS = sigmoidf(kcp.w + psp.y - th[j].w);
            bool o = (obits >> i) & 1u;
            float pom = o ? (1.0f - pS) : pS;        // P(y | mastered)
            float pou = o ? pG : (1.0f - pG);        // P(y | unmastered)
            float c1 = (1.0f - pF) * pom;
            float c2 = pT * pou;
            float c3 = pF * pom;
            float c4 = (1.0f - pT) * pou;
            sC[i][0][tid] = c1;
            sC[i][1][tid] = c2;
            sC[i][2][tid] = c3;
            sC[i][3][tid] = c4;

            // A = M * A,  M = [[c4,c3],[c2,c1]]
            float n00 = fmaf(c4, a00, c3 * a10);
            float n01 = fmaf(c4, a01, c3 * a11);
            float n10 = fmaf(c2, a00, c1 * a10);
            float n11 = fmaf(c2, a01, c1 * a11);
            a00 = n00; a01 = n01; a10 = n10; a11 = n11;
        }
    }
    {   // one normalization per 8-step segment
        float r = __fdividef(1.0f, a00 + a01 + a10 + a11);
        a00 *= r; a01 *= r; a10 *= r; a11 *= r;
    }

    // ---- inclusive warp scan of segment matrices ---------------------------
#pragma unroll
    for (int d = 1; d < 32; d <<= 1) {
        float b00 = __shfl_up_sync(0xFFFFFFFFu, a00, d);
        float b01 = __shfl_up_sync(0xFFFFFFFFu, a01, d);
        float b10 = __shfl_up_sync(0xFFFFFFFFu, a10, d);
        float b11 = __shfl_up_sync(0xFFFFFFFFu, a11, d);
        if (lane >= d) {
            float n00 = fmaf(a00, b00, a01 * b10);   // mine(later)*other(earlier)
            float n01 = fmaf(a00, b01, a01 * b11);
            float n10 = fmaf(a10, b00, a11 * b10);
            float n11 = fmaf(a10, b01, a11 * b11);
            float r = __fdividef(1.0f, n00 + n01 + n10 + n11);
            a00 = n00 * r; a01 = n01 * r; a10 = n10 * r; a11 = n11 * r;
        }
    }

    // warp0 publishes its row's total (lane 31 inclusive) for warp1
    if (warpInRow == 0 && lane == 31)
        w0tot[rowInCta] = make_float4(a00, a01, a10, a11);

    // exclusive prefix within this warp
    float e00 = __shfl_up_sync(0xFFFFFFFFu, a00, 1);
    float e01 = __shfl_up_sync(0xFFFFFFFFu, a01, 1);
    float e10 = __shfl_up_sync(0xFFFFFFFFu, a10, 1);
    float e11 = __shfl_up_sync(0xFFFFFFFFu, a11, 1);
    if (lane == 0) { e00 = 1.f; e01 = 0.f; e10 = 0.f; e11 = 1.f; }

    __syncthreads();

    if (warpInRow == 1) {
        // full exclusive = excl(this warp) * warp0_total   (later * earlier)
        float4 w0 = w0tot[rowInCta];
        float n00 = fmaf(e00, w0.x, e01 * w0.z);
        float n01 = fmaf(e00, w0.y, e01 * w0.w);
        float n10 = fmaf(e10, w0.x, e11 * w0.z);
        float n11 = fmaf(e10, w0.y, e11 * w0.w);
        e00 = n00; e01 = n01; e10 = n10; e11 = n11;
    }

    // state at this lane's segment start
    float hu0 = 1.0f - pL0;
    float hm0 = pL0;
    float hu = fmaf(e00, hu0, e01 * hm0);
    float hm = fmaf(e10, hu0, e11 * hm0);
    float rs = __fdividef(1.0f, hu + hm);
    hu *= rs; hm *= rs;

    // ---- pass 2: replay segment from sC, emit p_correct --------------------
    float* op = out + s0;
#pragma unroll
    for (int q = 0; q < SEG / 4; ++q) {
        float4 res;
        float* r4 = reinterpret_cast<float*>(&res);
#pragma unroll
        for (int j = 0; j < 4; ++j) {
            const int i = 4 * q + j;
            float c1 = sC[i][0][tid];
            float c2 = sC[i][1][tid];
            float c3 = sC[i][2][tid];
            float c4 = sC[i][3][tid];
            float nm = fmaf(c1, hm, c2 * hu);
            float nu = fmaf(c3, hm, c4 * hu);
            float r  = __fdividef(1.0f, nm + nu);
            hm = nm * r;
            hu = nu * r;
            bool o = (obits >> i) & 1u;
            float pom = c1 + c3;                   // = 1-pS if o else pS
            float pou = c2 + c4;                   // = pG   if o else 1-pG
            float c5 = o ? pom : (1.0f - pom);     // 1-pS
            float c6 = o ? pou : (1.0f - pou);     // pG
            r4[j] = fmaf(c5, hm, c6 * hu);
        }
        *reinterpret_cast<float4*>(op + 4 * q) = res;
    }
}

extern "C" void kernel_launch(void* const* d_in, const int* in_sizes, int n_in,
                              void* d_out, int out_size) {
    const float* pL0 = (const float*)d_in[0];
    const float* pT  = (const float*)d_in[1];
    const float* pF  = (const float*)d_in[2];
    const float* pG  = (const float*)d_in[3];
    const float* pS  = (const float*)d_in[4];
    const float* om  = (const float*)d_in[5];
    const float* sg  = (const float*)d_in[6];
    const float4* ab = (const float4*)d_in[7];
    const int* obs = (const int*)d_in[8];
    const int* kc  = (const int*)d_in[9];
    const int* pid = (const int*)d_in[10];
    const int* sid = (const int*)d_in[11];
    float* out = (float*)d_out;

    int K = in_sizes[0];                  // 1000
    int P = in_sizes[5];                  // 50000
    int B = in_sizes[8] / T_LEN;          // 8192 rows
    if (K > K_CAP) K = K_CAP;
    if (P > P_CAP) P = P_CAP;
    if (P < 1) P = 1;

    pack_ps<<<(P + 511) / 512, 512>>>(om, sg, P);

    int grid = (B + ROWS_PER_CTA - 1) / ROWS_PER_CTA;   // 2048
    bkt_warp_scan<<<grid, THREADS>>>(pL0, pT, pF, pG, pS, ab,
                                     obs, kc, pid, sid, out, B, K);
}